// round 7
// baseline (speedup 1.0000x reference)
#include <cuda_runtime.h>
#include <cuda_bf16.h>

// Problem constants
// B=32, S=12, F=128, K=8, H=64, C=64, N=512
// Math collapse: all N nodes share x[:, -1, :], so both GAT attentions are
// exactly uniform (softmax of a constant matrix) and att@Wh == Wh.
//   wh[b, k*H+h]  = sum_f x[b,11,f] * W_heads[k,f,h]
//   who[b, c]     = sum_{kh} elu(wh[b,kh]) * W_out[kh, c]
//   out[b, c']    = sum_c who[b,c] * (sum_n Wf[c', n*64 + c]) + bf[c']
// a1/a2 vectors are never needed.

__device__ float g_who[32 * 64];        // who[b][c]
__device__ float g_part[64 * 8 * 64];   // partial Wf row-sums [c'][chunk][c]

// ---------------------------------------------------------------------------
// K1: who[b,:]  (one block per batch, 512 threads)
// ---------------------------------------------------------------------------
__global__ __launch_bounds__(512) void k_who(
    const float* __restrict__ x,        // (32,12,128)
    const float* __restrict__ Wheads,   // (8,128,64)
    const float* __restrict__ Wout)     // (512,64)
{
    __shared__ float xs[128];
    __shared__ float hp[512];
    __shared__ float ps[512];
    const int b = blockIdx.x;
    const int t = threadIdx.x;

    if (t < 128) xs[t] = x[b * (12 * 128) + 11 * 128 + t];
    __syncthreads();

    // wh[t] with t = k*64 + h
    const int k  = t >> 6;
    const int hh = t & 63;
    const float* w = Wheads + k * (128 * 64) + hh;
    float acc = 0.f;
#pragma unroll 8
    for (int f = 0; f < 128; ++f)
        acc = fmaf(xs[f], __ldg(w + f * 64), acc);
    // ELU (alpha = 1)
    hp[t] = acc > 0.f ? acc : (expf(acc) - 1.f);
    __syncthreads();

    // who[c] = sum_{kh} hp[kh] * Wout[kh*64 + c], split across 8 segments
    const int c   = t & 63;
    const int seg = t >> 6;
    const float* wo = Wout + seg * (64 * 64) + c;
    float a2 = 0.f;
#pragma unroll 8
    for (int j = 0; j < 64; ++j)
        a2 = fmaf(hp[seg * 64 + j], __ldg(wo + j * 64), a2);
    ps[t] = a2;
    __syncthreads();

    if (t < 64) {
        float s = 0.f;
#pragma unroll
        for (int sg = 0; sg < 8; ++sg) s += ps[sg * 64 + t];
        g_who[b * 64 + t] = s;
    }
}

// ---------------------------------------------------------------------------
// K2: partial row-reduction of Wf (C=64 rows of 32768 floats each).
// grid = 64 rows * 8 chunks = 512 blocks, 256 threads, float4 loads.
// Chunk covers n in [chunk*64, chunk*64+64): 4096 contiguous floats = 1024 float4.
// float4 index p within chunk: n = p/16, c4 = p%16 (c = 4*c4 + comp).
// Thread t loads p = t + 256*j (j=0..3); p%16 == t%16 so c4 fixed per thread.
// ---------------------------------------------------------------------------
__global__ __launch_bounds__(256) void k_part(const float* __restrict__ Wf)
{
    const int cp    = blockIdx.x >> 3;  // c' row
    const int chunk = blockIdx.x & 7;
    const float4* base = reinterpret_cast<const float4*>(Wf + cp * 32768 + chunk * 4096);
    const int t = threadIdx.x;

    float4 acc = make_float4(0.f, 0.f, 0.f, 0.f);
#pragma unroll
    for (int j = 0; j < 4; ++j) {
        float4 v = __ldg(base + t + j * 256);
        acc.x += v.x; acc.y += v.y; acc.z += v.z; acc.w += v.w;
    }
    __shared__ float4 sa[256];
    sa[t] = acc;
    __syncthreads();

    if (t < 16) {
        float4 s = make_float4(0.f, 0.f, 0.f, 0.f);
#pragma unroll
        for (int m = 0; m < 16; ++m) {
            float4 v = sa[t + 16 * m];
            s.x += v.x; s.y += v.y; s.z += v.z; s.w += v.w;
        }
        float* dst = g_part + cp * 512 + chunk * 64 + 4 * t;
        dst[0] = s.x; dst[1] = s.y; dst[2] = s.z; dst[3] = s.w;
    }
}

// ---------------------------------------------------------------------------
// K3: reduce partials to Wfsum in smem (per block, redundantly — tiny) and
// compute out[b, c'] = sum_c who[b,c] * Wfsum[c',c] + bf[c'].
// grid = 32 (batch), 256 threads.
// ---------------------------------------------------------------------------
__global__ __launch_bounds__(256) void k_final(
    const float* __restrict__ bf, float* __restrict__ out)
{
    __shared__ float wfs[4096];   // Wfsum[c'][c]
    __shared__ float who_s[64];
    __shared__ float red[256];
    const int b = blockIdx.x;
    const int t = threadIdx.x;

    for (int e = t; e < 4096; e += 256) {
        const int cp = e >> 6, c = e & 63;
        float s = 0.f;
#pragma unroll
        for (int ch = 0; ch < 8; ++ch) s += g_part[cp * 512 + ch * 64 + c];
        wfs[e] = s;
    }
    if (t < 64) who_s[t] = g_who[b * 64 + t];
    __syncthreads();

    // t = part*64 + cp; each thread sums 16 c values for its (cp, part)
    const int cp   = t & 63;
    const int part = t >> 6;
    float acc = 0.f;
#pragma unroll
    for (int j = 0; j < 16; ++j) {
        const int c = part * 16 + j;
        acc = fmaf(who_s[c], wfs[cp * 64 + c], acc);
    }
    red[t] = acc;
    __syncthreads();

    if (t < 64) {
        float s = red[t] + red[64 + t] + red[128 + t] + red[192 + t] + __ldg(bf + t);
        out[b * 64 + t] = s;
    }
}

// ---------------------------------------------------------------------------
extern "C" void kernel_launch(void* const* d_in, const int* in_sizes, int n_in,
                              void* d_out, int out_size)
{
    // metadata order: x, W_heads, a1_heads, a2_heads, W_out, a1_out, a2_out, Wf, bf
    const float* x      = (const float*)d_in[0];
    const float* Wheads = (const float*)d_in[1];
    const float* Wout   = (const float*)d_in[4];
    const float* Wf     = (const float*)d_in[7];
    const float* bf     = (const float*)d_in[8];
    float* out = (float*)d_out;

    k_who  <<<32, 512>>>(x, Wheads, Wout);
    k_part <<<512, 256>>>(Wf);
    k_final<<<32, 256>>>(bf, out);
}

// round 9
// speedup vs baseline: 1.2211x; 1.2211x over previous
#include <cuda_runtime.h>
#include <cuda_bf16.h>

// B=32, S=12, F=128, K=8, H=64, C=64, N=512
// Math collapse: all N nodes share x[:, -1, :] -> both GAT softmaxes are
// exactly uniform and att@Wh == Wh. a1/a2 are dead inputs.
//   wh[b, k*H+h]  = sum_f x[b,11,f] * W_heads[k,f,h]   (then ELU)
//   who[b, c]     = sum_j elu_wh[b,j] * W_out[j, c]
//   out[b, c']    = sum_c who[b,c] * (sum_n Wf[c', n*64 + c]) + bf[c']

__device__ float g_wh [32 * 512];       // elu(wh)[b][j]
__device__ float g_who[32 * 64];        // who[b][c]
__device__ float g_part[64 * 8 * 64];   // partial Wf row-sums [c'][chunk][c]

__device__ __forceinline__ float4 f4add(float4 a, float4 b) {
    return make_float4(a.x + b.x, a.y + b.y, a.z + b.z, a.w + b.w);
}

// ---------------------------------------------------------------------------
// kA: elu(wh)[b, k*64 + h].  grid = 32*8 (b,k), 256 threads.
// t = fp*16 + h4: thread accumulates float4 over f in [fp*8, fp*8+8) for
// h = 4*h4..4*h4+3. All weight loads are contiguous float4 (row-major rows),
// 8 independent loads in flight per thread.
// ---------------------------------------------------------------------------
__global__ __launch_bounds__(256) void kA(
    const float* __restrict__ x,        // (32,12,128)
    const float* __restrict__ Wheads)   // (8,128,64)
{
    __shared__ float  xs[128];
    __shared__ float4 red[256];
    const int b = blockIdx.x >> 3;
    const int k = blockIdx.x & 7;
    const int t = threadIdx.x;

    if (t < 128) xs[t] = x[b * (12 * 128) + 11 * 128 + t];
    __syncthreads();

    const int h4 = t & 15;
    const int fp = t >> 4;
    const float4* wb = reinterpret_cast<const float4*>(Wheads + k * (128 * 64));

    float4 acc = make_float4(0.f, 0.f, 0.f, 0.f);
#pragma unroll
    for (int i = 0; i < 8; ++i) {
        const int f = fp * 8 + i;
        const float4 w = __ldg(wb + f * 16 + h4);
        const float xv = xs[f];
        acc.x = fmaf(xv, w.x, acc.x);
        acc.y = fmaf(xv, w.y, acc.y);
        acc.z = fmaf(xv, w.z, acc.z);
        acc.w = fmaf(xv, w.w, acc.w);
    }
    red[t] = acc;
    __syncthreads();
    if (t < 128) red[t] = f4add(red[t], red[t + 128]);
    __syncthreads();
    if (t < 64)  red[t] = f4add(red[t], red[t + 64]);
    __syncthreads();
    if (t < 32)  red[t] = f4add(red[t], red[t + 32]);
    __syncthreads();
    if (t < 16) {
        float4 s = f4add(red[t], red[t + 16]);
        // ELU (alpha = 1)
        s.x = s.x > 0.f ? s.x : (expf(s.x) - 1.f);
        s.y = s.y > 0.f ? s.y : (expf(s.y) - 1.f);
        s.z = s.z > 0.f ? s.z : (expf(s.z) - 1.f);
        s.w = s.w > 0.f ? s.w : (expf(s.w) - 1.f);
        reinterpret_cast<float4*>(g_wh + b * 512 + k * 64)[t] = s;
    }
}

// ---------------------------------------------------------------------------
// kB: who[b,c] = sum_j g_wh[b,j] * W_out[j,c].  grid = 32 (b), 256 threads.
// t = jp*16 + c4: float4 over j in [jp*32, jp*32+32), c = 4*c4..+3.
// 32 independent float4 loads per thread, all contiguous rows.
// ---------------------------------------------------------------------------
__global__ __launch_bounds__(256) void kB(const float* __restrict__ Wout) // (512,64)
{
    __shared__ float  hps[512];
    __shared__ float4 red[256];
    const int b = blockIdx.x;
    const int t = threadIdx.x;

    hps[t]       = g_wh[b * 512 + t];
    hps[t + 256] = g_wh[b * 512 + 256 + t];
    __syncthreads();

    const int c4 = t & 15;
    const int jp = t >> 4;
    const float4* wo = reinterpret_cast<const float4*>(Wout);

    float4 acc = make_float4(0.f, 0.f, 0.f, 0.f);
#pragma unroll 8
    for (int i = 0; i < 32; ++i) {
        const int j = jp * 32 + i;
        const float4 w = __ldg(wo + j * 16 + c4);
        const float hv = hps[j];
        acc.x = fmaf(hv, w.x, acc.x);
        acc.y = fmaf(hv, w.y, acc.y);
        acc.z = fmaf(hv, w.z, acc.z);
        acc.w = fmaf(hv, w.w, acc.w);
    }
    red[t] = acc;
    __syncthreads();
    if (t < 128) red[t] = f4add(red[t], red[t + 128]);
    __syncthreads();
    if (t < 64)  red[t] = f4add(red[t], red[t + 64]);
    __syncthreads();
    if (t < 32)  red[t] = f4add(red[t], red[t + 32]);
    __syncthreads();
    if (t < 16) {
        const float4 s = f4add(red[t], red[t + 16]);
        reinterpret_cast<float4*>(g_who + b * 64)[t] = s;
    }
}

// ---------------------------------------------------------------------------
// k_part: partial row-reduction of Wf (64 rows x 32768 floats).
// grid = 64*8 blocks, 256 threads, float4 streaming loads (DRAM-bound, 8MB).
// ---------------------------------------------------------------------------
__global__ __launch_bounds__(256) void k_part(const float* __restrict__ Wf)
{
    const int cp    = blockIdx.x >> 3;
    const int chunk = blockIdx.x & 7;
    const float4* base = reinterpret_cast<const float4*>(Wf + cp * 32768 + chunk * 4096);
    const int t = threadIdx.x;

    float4 acc = make_float4(0.f, 0.f, 0.f, 0.f);
#pragma unroll
    for (int j = 0; j < 4; ++j) {
        const float4 v = __ldg(base + t + j * 256);
        acc.x += v.x; acc.y += v.y; acc.z += v.z; acc.w += v.w;
    }
    __shared__ float4 sa[256];
    sa[t] = acc;
    __syncthreads();

    if (t < 16) {
        float4 s = make_float4(0.f, 0.f, 0.f, 0.f);
#pragma unroll
        for (int m = 0; m < 16; ++m) s = f4add(s, sa[t + 16 * m]);
        float* dst = g_part + cp * 512 + chunk * 64 + 4 * t;
        dst[0] = s.x; dst[1] = s.y; dst[2] = s.z; dst[3] = s.w;
    }
}

// ---------------------------------------------------------------------------
// k_final: Wfsum in smem (redundant per block, tiny) + 64x64 GEMV + bias.
// grid = 32 (b), 256 threads.
// ---------------------------------------------------------------------------
__global__ __launch_bounds__(256) void k_final(
    const float* __restrict__ bf, float* __restrict__ out)
{
    __shared__ float wfs[4096];
    __shared__ float who_s[64];
    __shared__ float red[256];
    const int b = blockIdx.x;
    const int t = threadIdx.x;

    for (int e = t; e < 4096; e += 256) {
        const int cp = e >> 6, c = e & 63;
        float s = 0.f;
#pragma unroll
        for (int ch = 0; ch < 8; ++ch) s += g_part[cp * 512 + ch * 64 + c];
        wfs[e] = s;
    }
    if (t < 64) who_s[t] = g_who[b * 64 + t];
    __syncthreads();

    const int cp   = t & 63;
    const int part = t >> 6;
    float acc = 0.f;
#pragma unroll
    for (int j = 0; j < 16; ++j) {
        const int c = part * 16 + j;
        acc = fmaf(who_s[c], wfs[cp * 64 + c], acc);
    }
    red[t] = acc;
    __syncthreads();

    if (t < 64) {
        out[b * 64 + t] = red[t] + red[64 + t] + red[128 + t] + red[192 + t]
                        + __ldg(bf + t);
    }
}

// ---------------------------------------------------------------------------
extern "C" void kernel_launch(void* const* d_in, const int* in_sizes, int n_in,
                              void* d_out, int out_size)
{
    // metadata order: x, W_heads, a1_heads, a2_heads, W_out, a1_out, a2_out, Wf, bf
    const float* x      = (const float*)d_in[0];
    const float* Wheads = (const float*)d_in[1];
    const float* Wout   = (const float*)d_in[4];
    const float* Wf     = (const float*)d_in[7];
    const float* bf     = (const float*)d_in[8];
    float* out = (float*)d_out;

    k_part <<<512, 256>>>(Wf);          // independent chain, biggest memory mover
    kA     <<<256, 256>>>(x, Wheads);
    kB     <<<32,  256>>>(Wout);
    k_final<<<32,  256>>>(bf, out);
}

// round 13
// speedup vs baseline: 1.3190x; 1.0802x over previous
#include <cuda_runtime.h>
#include <cuda_bf16.h>

// B=32, S=12, F=128, K=8, H=64, C=64, N=512
// Math collapse: all N nodes share x[:, -1, :] -> both GAT softmaxes are
// exactly uniform and att@Wh == Wh. a1/a2 are dead inputs.
//   wh[b, k*H+h]  = sum_f x[b,11,f] * W_heads[k,f,h]   (then ELU)
//   who[b, c]     = sum_j elu_wh[b,j] * W_out[j, c]
//   out[b, c']    = sum_c who[b,c] * (sum_n Wf[c', n*64 + c]) + bf[c']

__device__ float g_wh [32 * 512];       // elu(wh)[b][j]
__device__ float g_part[64 * 8 * 64];   // partial Wf row-sums [c'][chunk][c]

__device__ __forceinline__ float4 f4add(float4 a, float4 b) {
    return make_float4(a.x + b.x, a.y + b.y, a.z + b.z, a.w + b.w);
}

// ---------------------------------------------------------------------------
// kA: elu(wh)[b, k*64 + h].  grid = 32*8 (b,k), 256 threads.
// t = fp*16 + h4: float4 over h, partial over f; contiguous float4 loads,
// 8 independent loads in flight per thread.
// ---------------------------------------------------------------------------
__global__ __launch_bounds__(256) void kA(
    const float* __restrict__ x,        // (32,12,128)
    const float* __restrict__ Wheads)   // (8,128,64)
{
    __shared__ float  xs[128];
    __shared__ float4 red[256];
    const int b = blockIdx.x >> 3;
    const int k = blockIdx.x & 7;
    const int t = threadIdx.x;

    if (t < 128) xs[t] = x[b * (12 * 128) + 11 * 128 + t];
    __syncthreads();

    const int h4 = t & 15;
    const int fp = t >> 4;
    const float4* wb = reinterpret_cast<const float4*>(Wheads + k * (128 * 64));

    float4 acc = make_float4(0.f, 0.f, 0.f, 0.f);
#pragma unroll
    for (int i = 0; i < 8; ++i) {
        const int f = fp * 8 + i;
        const float4 w = __ldg(wb + f * 16 + h4);
        const float xv = xs[f];
        acc.x = fmaf(xv, w.x, acc.x);
        acc.y = fmaf(xv, w.y, acc.y);
        acc.z = fmaf(xv, w.z, acc.z);
        acc.w = fmaf(xv, w.w, acc.w);
    }
    red[t] = acc;
    __syncthreads();
    if (t < 128) red[t] = f4add(red[t], red[t + 128]);
    __syncthreads();
    if (t < 64)  red[t] = f4add(red[t], red[t + 64]);
    __syncthreads();
    if (t < 32)  red[t] = f4add(red[t], red[t + 32]);
    __syncthreads();
    if (t < 16) {
        float4 s = f4add(red[t], red[t + 16]);
        // ELU (alpha = 1)
        s.x = s.x > 0.f ? s.x : (expf(s.x) - 1.f);
        s.y = s.y > 0.f ? s.y : (expf(s.y) - 1.f);
        s.z = s.z > 0.f ? s.z : (expf(s.z) - 1.f);
        s.w = s.w > 0.f ? s.w : (expf(s.w) - 1.f);
        reinterpret_cast<float4*>(g_wh + b * 512 + k * 64)[t] = s;
    }
}

// ---------------------------------------------------------------------------
// k_part: partial row-reduction of Wf (64 rows x 32768 floats).
// grid = 64*8 blocks, 256 threads, float4 streaming loads (DRAM-bound, 8MB).
// ---------------------------------------------------------------------------
__global__ __launch_bounds__(256) void k_part(const float* __restrict__ Wf)
{
    const int cp    = blockIdx.x >> 3;
    const int chunk = blockIdx.x & 7;
    const float4* base = reinterpret_cast<const float4*>(Wf + cp * 32768 + chunk * 4096);
    const int t = threadIdx.x;

    float4 acc = make_float4(0.f, 0.f, 0.f, 0.f);
#pragma unroll
    for (int j = 0; j < 4; ++j) {
        const float4 v = __ldg(base + t + j * 256);
        acc.x += v.x; acc.y += v.y; acc.z += v.z; acc.w += v.w;
    }
    __shared__ float4 sa[256];
    sa[t] = acc;
    __syncthreads();

    if (t < 16) {
        float4 s = make_float4(0.f, 0.f, 0.f, 0.f);
#pragma unroll
        for (int m = 0; m < 16; ++m) s = f4add(s, sa[t + 16 * m]);
        float* dst = g_part + cp * 512 + chunk * 64 + 4 * t;
        dst[0] = s.x; dst[1] = s.y; dst[2] = s.z; dst[3] = s.w;
    }
}

// ---------------------------------------------------------------------------
// kBF: fused  who[b,:] = elu_wh[b,:] @ W_out   and
//             out[b,:] = who[b,:] @ Wfsum^T + bf
// grid = 32 (b), 256 threads.
// wfs built from g_part with 32 independent float4 L2 loads per thread,
// issued BEFORE the who-reduction barriers so latency overlaps them.
// wfs rows padded to 65 floats -> conflict-free reads in final GEMV.
// ---------------------------------------------------------------------------
__global__ __launch_bounds__(256) void kBF(
    const float* __restrict__ Wout,     // (512,64)
    const float* __restrict__ bf,       // (64)
    float* __restrict__ out)            // (32,64)
{
    __shared__ float  hps[512];
    __shared__ float4 red[256];
    __shared__ float  wfs[64 * 65];     // Wfsum[cp][c], padded
    __shared__ float  who_s[64];
    __shared__ float  red2[256];
    const int b = blockIdx.x;
    const int t = threadIdx.x;

    hps[t]       = g_wh[b * 512 + t];
    hps[t + 256] = g_wh[b * 512 + 256 + t];
    __syncthreads();

    // --- who GEMV partial: t = jp*16 + c4, float4 over c, partial over j ---
    const int c4 = t & 15;
    const int jp = t >> 4;
    const float4* wo = reinterpret_cast<const float4*>(Wout);
    float4 acc = make_float4(0.f, 0.f, 0.f, 0.f);
#pragma unroll 8
    for (int i = 0; i < 32; ++i) {
        const int j = jp * 32 + i;
        const float4 w = __ldg(wo + j * 16 + c4);
        const float hv = hps[j];
        acc.x = fmaf(hv, w.x, acc.x);
        acc.y = fmaf(hv, w.y, acc.y);
        acc.z = fmaf(hv, w.z, acc.z);
        acc.w = fmaf(hv, w.w, acc.w);
    }
    red[t] = acc;

    // --- wfs chunk-sum (independent of red; overlaps the barriers below) ---
    const float4* gp4 = reinterpret_cast<const float4*>(g_part); // [cp*128 + ch*16 + c4]
#pragma unroll
    for (int p = 0; p < 4; ++p) {
        const int idx = p * 256 + t;        // float4 index in [0, 1024)
        const int cp  = idx >> 4;
        const int cc4 = idx & 15;
        float4 s = make_float4(0.f, 0.f, 0.f, 0.f);
#pragma unroll
        for (int ch = 0; ch < 8; ++ch)
            s = f4add(s, __ldg(gp4 + cp * 128 + ch * 16 + cc4));
        float* w = wfs + cp * 65 + 4 * cc4;
        w[0] = s.x; w[1] = s.y; w[2] = s.z; w[3] = s.w;
    }
    __syncthreads();

    // --- reduce who partials ---
    if (t < 128) red[t] = f4add(red[t], red[t + 128]);
    __syncthreads();
    if (t < 64)  red[t] = f4add(red[t], red[t + 64]);
    __syncthreads();
    if (t < 32)  red[t] = f4add(red[t], red[t + 32]);
    __syncthreads();
    if (t < 16) {
        const float4 s = f4add(red[t], red[t + 16]);
        who_s[4 * t + 0] = s.x;
        who_s[4 * t + 1] = s.y;
        who_s[4 * t + 2] = s.z;
        who_s[4 * t + 3] = s.w;
    }
    __syncthreads();

    // --- final GEMV: t = part*64 + cp, each thread 16 fmas from smem ---
    const int cp   = t & 63;
    const int part = t >> 6;
    float a = 0.f;
#pragma unroll
    for (int j = 0; j < 16; ++j) {
        const int c = part * 16 + j;
        a = fmaf(who_s[c], wfs[cp * 65 + c], a);
    }
    red2[t] = a;
    __syncthreads();

    if (t < 64) {
        out[b * 64 + t] = red2[t] + red2[64 + t] + red2[128 + t] + red2[192 + t]
                        + __ldg(bf + t);
    }
}

// ---------------------------------------------------------------------------
extern "C" void kernel_launch(void* const* d_in, const int* in_sizes, int n_in,
                              void* d_out, int out_size)
{
    // metadata order: x, W_heads, a1_heads, a2_heads, W_out, a1_out, a2_out, Wf, bf
    const float* x      = (const float*)d_in[0];
    const float* Wheads = (const float*)d_in[1];
    const float* Wout   = (const float*)d_in[4];
    const float* Wf     = (const float*)d_in[7];
    const float* bf     = (const float*)d_in[8];
    float* out = (float*)d_out;

    k_part <<<512, 256>>>(Wf);          // biggest memory mover first
    kA     <<<256, 256>>>(x, Wheads);
    kBF    <<<32,  256>>>(Wout, bf, out);
}

// round 15
// speedup vs baseline: 1.5237x; 1.1552x over previous
#include <cuda_runtime.h>
#include <cuda_bf16.h>

// B=32, S=12, F=128, K=8, H=64, C=64, N=512
// Math collapse: all N nodes share x[:, -1, :] -> both GAT softmaxes are
// exactly uniform and att@Wh == Wh. a1/a2 are dead inputs.
//   wh[b, k*H+h]  = sum_f x[b,11,f] * W_heads[k,f,h]   (then ELU)
//   who[b, c]     = sum_j elu_wh[b,j] * W_out[j, c]
//   out[b, c']    = sum_c who[b,c] * (sum_n Wf[c', n*64 + c]) + bf[c']
//
// Single fused kernel, 800 blocks:
//   blocks [0,512)   : Wf partial row-reduction -> g_part   (DRAM stream, 8MB)
//   blocks [512,768) : elu(wh) -> g_wh                      (L2 GEMV)
//   blocks [768,800) : who GEMV + Wfsum + final GEMV -> out (gated on counters)
// Consumers have the highest block ids => producers always scheduled first =>
// spin-wait is deadlock-free at any occupancy. Counters reset by the last
// consumer block so graph replays are deterministic.

__device__ float g_wh [32 * 512];       // elu(wh)[b][j]
__device__ float g_part[64 * 8 * 64];   // partial Wf row-sums [c'][chunk][c]
__device__ int   g_c1;                  // k_part blocks done (512)
__device__ int   g_c2;                  // kA blocks done (256)
__device__ int   g_done;                // consumer blocks done (32)

__device__ __forceinline__ float4 f4add(float4 a, float4 b) {
    return make_float4(a.x + b.x, a.y + b.y, a.z + b.z, a.w + b.w);
}

// shared pool layout (consumer branch is the largest user):
//   [0,2048)       hps[512]f      | kA: xs[128]f | k_part: sa[256]f4 (4KB, ok)
//   [2048,6144)    red[256]f4     | kA: red[256]f4
//   [6144,22784)   wfs[64*65]f
//   [22784,23040)  who_s[64]f
//   [23040,24064)  red2[256]f
#define POOL_BYTES 24064

__global__ __launch_bounds__(256) void k_fused(
    const float* __restrict__ x,        // (32,12,128)
    const float* __restrict__ Wheads,   // (8,128,64)
    const float* __restrict__ Wout,     // (512,64)
    const float* __restrict__ Wf,       // (64, 32768)
    const float* __restrict__ bf,       // (64)
    float* __restrict__ out)            // (32,64)
{
    __shared__ __align__(16) char pool[POOL_BYTES];
    const int bid = blockIdx.x;
    const int t   = threadIdx.x;

    if (bid < 512) {
        // ------------------- k_part: Wf partial row-reduction -------------------
        float4* sa = reinterpret_cast<float4*>(pool);
        const int cp    = bid >> 3;
        const int chunk = bid & 7;
        const float4* base = reinterpret_cast<const float4*>(Wf + cp * 32768 + chunk * 4096);

        float4 acc = make_float4(0.f, 0.f, 0.f, 0.f);
#pragma unroll
        for (int j = 0; j < 4; ++j) {
            const float4 v = __ldg(base + t + j * 256);
            acc.x += v.x; acc.y += v.y; acc.z += v.z; acc.w += v.w;
        }
        sa[t] = acc;
        __syncthreads();

        if (t < 16) {
            float4 s = make_float4(0.f, 0.f, 0.f, 0.f);
#pragma unroll
            for (int m = 0; m < 16; ++m) s = f4add(s, sa[t + 16 * m]);
            float* dst = g_part + cp * 512 + chunk * 64 + 4 * t;
            dst[0] = s.x; dst[1] = s.y; dst[2] = s.z; dst[3] = s.w;
        }
        __syncthreads();
        if (t == 0) { __threadfence(); atomicAdd(&g_c1, 1); }

    } else if (bid < 768) {
        // ------------------------ kA: elu(wh) -> g_wh ---------------------------
        float*  xs  = reinterpret_cast<float*>(pool);
        float4* red = reinterpret_cast<float4*>(pool + 2048);
        const int bk = bid - 512;
        const int b  = bk >> 3;
        const int k  = bk & 7;

        if (t < 128) xs[t] = x[b * (12 * 128) + 11 * 128 + t];
        __syncthreads();

        const int h4 = t & 15;
        const int fp = t >> 4;
        const float4* wb = reinterpret_cast<const float4*>(Wheads + k * (128 * 64));

        float4 acc = make_float4(0.f, 0.f, 0.f, 0.f);
#pragma unroll
        for (int i = 0; i < 8; ++i) {
            const int f = fp * 8 + i;
            const float4 w = __ldg(wb + f * 16 + h4);
            const float xv = xs[f];
            acc.x = fmaf(xv, w.x, acc.x);
            acc.y = fmaf(xv, w.y, acc.y);
            acc.z = fmaf(xv, w.z, acc.z);
            acc.w = fmaf(xv, w.w, acc.w);
        }
        red[t] = acc;
        __syncthreads();
        if (t < 128) red[t] = f4add(red[t], red[t + 128]);
        __syncthreads();
        if (t < 64)  red[t] = f4add(red[t], red[t + 64]);
        __syncthreads();
        if (t < 32)  red[t] = f4add(red[t], red[t + 32]);
        __syncthreads();
        if (t < 16) {
            float4 s = f4add(red[t], red[t + 16]);
            // ELU (alpha = 1)
            s.x = s.x > 0.f ? s.x : (expf(s.x) - 1.f);
            s.y = s.y > 0.f ? s.y : (expf(s.y) - 1.f);
            s.z = s.z > 0.f ? s.z : (expf(s.z) - 1.f);
            s.w = s.w > 0.f ? s.w : (expf(s.w) - 1.f);
            reinterpret_cast<float4*>(g_wh + b * 512 + k * 64)[t] = s;
        }
        __syncthreads();
        if (t == 0) { __threadfence(); atomicAdd(&g_c2, 1); }

    } else {
        // --------------- kBF: who GEMV + Wfsum + final GEMV -> out --------------
        float*  hps   = reinterpret_cast<float*>(pool);
        float4* red   = reinterpret_cast<float4*>(pool + 2048);
        float*  wfs   = reinterpret_cast<float*>(pool + 6144);
        float*  who_s = reinterpret_cast<float*>(pool + 22784);
        float*  red2  = reinterpret_cast<float*>(pool + 23040);
        const int b = bid - 768;

        // gate on kA producers (g_wh ready)
        if (t == 0) {
            while (atomicAdd(&g_c2, 0) < 256) __nanosleep(64);
            __threadfence();
        }
        __syncthreads();

        hps[t]       = g_wh[b * 512 + t];
        hps[t + 256] = g_wh[b * 512 + 256 + t];
        __syncthreads();

        // who partial: t = jp*16 + c4, float4 over c, partial over j
        const int c4 = t & 15;
        const int jp = t >> 4;
        const float4* wo = reinterpret_cast<const float4*>(Wout);
        float4 acc = make_float4(0.f, 0.f, 0.f, 0.f);
#pragma unroll 8
        for (int i = 0; i < 32; ++i) {
            const int j = jp * 32 + i;
            const float4 w = __ldg(wo + j * 16 + c4);
            const float hv = hps[j];
            acc.x = fmaf(hv, w.x, acc.x);
            acc.y = fmaf(hv, w.y, acc.y);
            acc.z = fmaf(hv, w.z, acc.z);
            acc.w = fmaf(hv, w.w, acc.w);
        }
        red[t] = acc;

        // gate on k_part producers (g_part ready)
        if (t == 0) {
            while (atomicAdd(&g_c1, 0) < 512) __nanosleep(64);
            __threadfence();
        }
        __syncthreads();

        // wfs chunk-sum: 32 independent float4 L2 loads per thread
        const float4* gp4 = reinterpret_cast<const float4*>(g_part);
#pragma unroll
        for (int p = 0; p < 4; ++p) {
            const int idx = p * 256 + t;        // float4 index in [0, 1024)
            const int cp  = idx >> 4;
            const int cc4 = idx & 15;
            float4 s = make_float4(0.f, 0.f, 0.f, 0.f);
#pragma unroll
            for (int ch = 0; ch < 8; ++ch)
                s = f4add(s, gp4[cp * 128 + ch * 16 + cc4]);
            float* w = wfs + cp * 65 + 4 * cc4;
            w[0] = s.x; w[1] = s.y; w[2] = s.z; w[3] = s.w;
        }
        __syncthreads();

        // reduce who partials
        if (t < 128) red[t] = f4add(red[t], red[t + 128]);
        __syncthreads();
        if (t < 64)  red[t] = f4add(red[t], red[t + 64]);
        __syncthreads();
        if (t < 32)  red[t] = f4add(red[t], red[t + 32]);
        __syncthreads();
        if (t < 16) {
            const float4 s = f4add(red[t], red[t + 16]);
            who_s[4 * t + 0] = s.x;
            who_s[4 * t + 1] = s.y;
            who_s[4 * t + 2] = s.z;
            who_s[4 * t + 3] = s.w;
        }
        __syncthreads();

        // final GEMV: t = part*64 + cp
        const int cp   = t & 63;
        const int part = t >> 6;
        float a = 0.f;
#pragma unroll
        for (int j = 0; j < 16; ++j) {
            const int c = part * 16 + j;
            a = fmaf(who_s[c], wfs[cp * 65 + c], a);
        }
        red2[t] = a;
        __syncthreads();

        if (t < 64) {
            out[b * 64 + t] = red2[t] + red2[64 + t] + red2[128 + t] + red2[192 + t]
                            + __ldg(bf + t);
        }
        __syncthreads();

        // last consumer resets counters for the next graph replay
        if (t == 0) {
            const int d = atomicAdd(&g_done, 1);
            if (d == 31) {
                atomicExch(&g_c1, 0);
                atomicExch(&g_c2, 0);
                atomicExch(&g_done, 0);
            }
        }
    }
}

// ---------------------------------------------------------------------------
extern "C" void kernel_launch(void* const* d_in, const int* in_sizes, int n_in,
                              void* d_out, int out_size)
{
    // metadata order: x, W_heads, a1_heads, a2_heads, W_out, a1_out, a2_out, Wf, bf
    const float* x      = (const float*)d_in[0];
    const float* Wheads = (const float*)d_in[1];
    const float* Wout   = (const float*)d_in[4];
    const float* Wf     = (const float*)d_in[7];
    const float* bf     = (const float*)d_in[8];
    float* out = (float*)d_out;

    k_fused<<<800, 256>>>(x, Wheads, Wout, Wf, bf, out);
}

// round 16
// speedup vs baseline: 1.7719x; 1.1629x over previous
#include <cuda_runtime.h>
#include <cuda_bf16.h>

// B=32, S=12, F=128, K=8, H=64, C=64, N=512
// Math collapse: all N nodes share x[:, -1, :] -> both GAT softmaxes are
// exactly uniform and att@Wh == Wh. a1/a2 are dead inputs.
//   wh[b, k*H+h]  = sum_f x[b,11,f] * W_heads[k,f,h]   (then ELU)
//   who[b, c]     = sum_j elu_wh[b,j] * W_out[j, c]
//   out[b, c']    = sum_c who[b,c] * Wfsum[c',c] + bf[c'],
//   Wfsum[c',c]   = sum_n Wf[c', n*64 + c]
//
// Single fused kernel, 816 blocks:
//   [0,512)   P1: Wf partial row-reduction -> g_part        (DRAM/L2 stream)
//   [512,768) P2: elu(wh) -> g_wh                           (L2 GEMV)
//   [768,784) M : g_part -> g_wfsum (1 thread/output, 8 indep scalar loads)
//   [784,816) C : who GEMV + final GEMV -> out
// Consumers have the highest block ids => producers scheduled first => spins
// are deadlock-free. Counters reset by last consumer block (deterministic
// across graph replays; no float atomics anywhere).

__device__ float g_wh   [32 * 512];     // elu(wh)[b][j]
__device__ float g_part [64 * 8 * 64];  // partial Wf row-sums [c'][chunk][c]
__device__ float g_wfsum[64 * 64];      // Wfsum[c'][c]
__device__ int   g_c1;                  // P1 blocks done (512)
__device__ int   g_c2;                  // P2 blocks done (256)
__device__ int   g_c3;                  // M blocks done (16)
__device__ int   g_done;                // C blocks done (32)

__device__ __forceinline__ float4 f4add(float4 a, float4 b) {
    return make_float4(a.x + b.x, a.y + b.y, a.z + b.z, a.w + b.w);
}

// shared pool (consumer branch is the largest user):
//   [0,2048)       hps[512]f      | P2: xs[128]f | P1: sa[256]f4 (4KB ok)
//   [2048,6144)    red[256]f4     | P2: red[256]f4
//   [6144,22784)   wfs[64*65]f (padded rows -> conflict-free final GEMV)
//   [22784,23040)  who_s[64]f
//   [23040,24064)  red2[256]f
#define POOL_BYTES 24064

__global__ __launch_bounds__(256) void k_fused(
    const float* __restrict__ x,        // (32,12,128)
    const float* __restrict__ Wheads,   // (8,128,64)
    const float* __restrict__ Wout,     // (512,64)
    const float* __restrict__ Wf,       // (64, 32768)
    const float* __restrict__ bf,       // (64)
    float* __restrict__ out)            // (32,64)
{
    __shared__ __align__(16) char pool[POOL_BYTES];
    const int bid = blockIdx.x;
    const int t   = threadIdx.x;

    if (bid < 512) {
        // ---------------- P1: Wf partial row-reduction -> g_part ----------------
        float4* sa = reinterpret_cast<float4*>(pool);
        const int cp    = bid >> 3;
        const int chunk = bid & 7;
        const float4* base = reinterpret_cast<const float4*>(Wf + cp * 32768 + chunk * 4096);

        float4 v0 = __ldg(base + t);
        float4 v1 = __ldg(base + t + 256);
        float4 v2 = __ldg(base + t + 512);
        float4 v3 = __ldg(base + t + 768);
        sa[t] = f4add(f4add(v0, v1), f4add(v2, v3));
        __syncthreads();

        if (t < 16) {
            float4 s = make_float4(0.f, 0.f, 0.f, 0.f);
#pragma unroll
            for (int m = 0; m < 16; ++m) s = f4add(s, sa[t + 16 * m]);
            float* dst = g_part + cp * 512 + chunk * 64 + 4 * t;
            dst[0] = s.x; dst[1] = s.y; dst[2] = s.z; dst[3] = s.w;
        }
        __syncthreads();
        if (t == 0) { __threadfence(); atomicAdd(&g_c1, 1); }

    } else if (bid < 768) {
        // --------------------- P2: elu(wh) -> g_wh ------------------------------
        float*  xs  = reinterpret_cast<float*>(pool);
        float4* red = reinterpret_cast<float4*>(pool + 2048);
        const int bk = bid - 512;
        const int b  = bk >> 3;
        const int k  = bk & 7;

        if (t < 128) xs[t] = x[b * (12 * 128) + 11 * 128 + t];
        __syncthreads();

        const int h4 = t & 15;
        const int fp = t >> 4;
        const float4* wb = reinterpret_cast<const float4*>(Wheads + k * (128 * 64));

        float4 acc = make_float4(0.f, 0.f, 0.f, 0.f);
#pragma unroll
        for (int i = 0; i < 8; ++i) {
            const int f = fp * 8 + i;
            const float4 w = __ldg(wb + f * 16 + h4);
            const float xv = xs[f];
            acc.x = fmaf(xv, w.x, acc.x);
            acc.y = fmaf(xv, w.y, acc.y);
            acc.z = fmaf(xv, w.z, acc.z);
            acc.w = fmaf(xv, w.w, acc.w);
        }
        red[t] = acc;
        __syncthreads();
        if (t < 128) red[t] = f4add(red[t], red[t + 128]);
        __syncthreads();
        if (t < 64)  red[t] = f4add(red[t], red[t + 64]);
        __syncthreads();
        if (t < 32)  red[t] = f4add(red[t], red[t + 32]);
        __syncthreads();
        if (t < 16) {
            float4 s = f4add(red[t], red[t + 16]);
            // ELU (alpha = 1)
            s.x = s.x > 0.f ? s.x : (expf(s.x) - 1.f);
            s.y = s.y > 0.f ? s.y : (expf(s.y) - 1.f);
            s.z = s.z > 0.f ? s.z : (expf(s.z) - 1.f);
            s.w = s.w > 0.f ? s.w : (expf(s.w) - 1.f);
            reinterpret_cast<float4*>(g_wh + b * 512 + k * 64)[t] = s;
        }
        __syncthreads();
        if (t == 0) { __threadfence(); atomicAdd(&g_c2, 1); }

    } else if (bid < 784) {
        // ------------- M: g_part -> g_wfsum (one thread per output) -------------
        if (t == 0) {
            while (atomicAdd(&g_c1, 0) < 512) __nanosleep(32);
            __threadfence();
        }
        __syncthreads();

        const int gid = (bid - 768) * 256 + t;   // [0, 4096)
        const int cp  = gid >> 6;
        const int c   = gid & 63;
        const float* p = g_part + cp * 512 + c;
        // 8 independent scalar loads, tree-summed (MLP = 8)
        const float a0 = __ldg(p);
        const float a1 = __ldg(p + 64);
        const float a2 = __ldg(p + 128);
        const float a3 = __ldg(p + 192);
        const float a4 = __ldg(p + 256);
        const float a5 = __ldg(p + 320);
        const float a6 = __ldg(p + 384);
        const float a7 = __ldg(p + 448);
        g_wfsum[gid] = ((a0 + a1) + (a2 + a3)) + ((a4 + a5) + (a6 + a7));
        __syncthreads();
        if (t == 0) { __threadfence(); atomicAdd(&g_c3, 1); }

    } else {
        // ---------------- C: who GEMV + final GEMV -> out -----------------------
        float*  hps   = reinterpret_cast<float*>(pool);
        float4* red   = reinterpret_cast<float4*>(pool + 2048);
        float*  wfs   = reinterpret_cast<float*>(pool + 6144);   // [64][65]
        float*  who_s = reinterpret_cast<float*>(pool + 22784);
        float*  red2  = reinterpret_cast<float*>(pool + 23040);
        const int b = bid - 784;

        // gate on P2 (g_wh ready)
        if (t == 0) {
            while (atomicAdd(&g_c2, 0) < 256) __nanosleep(32);
            __threadfence();
        }
        __syncthreads();

        hps[t]       = g_wh[b * 512 + t];
        hps[t + 256] = g_wh[b * 512 + 256 + t];
        __syncthreads();

        // who partial: t = jp*16 + c4; 4 independent accumulators (chain 8)
        const int c4 = t & 15;
        const int jp = t >> 4;
        const float4* wo = reinterpret_cast<const float4*>(Wout);
        float4 a0 = make_float4(0.f, 0.f, 0.f, 0.f);
        float4 a1 = a0, a2 = a0, a3 = a0;
#pragma unroll
        for (int i = 0; i < 8; ++i) {
            const int j = jp * 32 + i;
            const float4 w0 = __ldg(wo + (j     ) * 16 + c4);
            const float4 w1 = __ldg(wo + (j +  8) * 16 + c4);
            const float4 w2 = __ldg(wo + (j + 16) * 16 + c4);
            const float4 w3 = __ldg(wo + (j + 24) * 16 + c4);
            const float h0 = hps[j], h1 = hps[j + 8], h2 = hps[j + 16], h3 = hps[j + 24];
            a0.x = fmaf(h0, w0.x, a0.x); a0.y = fmaf(h0, w0.y, a0.y);
            a0.z = fmaf(h0, w0.z, a0.z); a0.w = fmaf(h0, w0.w, a0.w);
            a1.x = fmaf(h1, w1.x, a1.x); a1.y = fmaf(h1, w1.y, a1.y);
            a1.z = fmaf(h1, w1.z, a1.z); a1.w = fmaf(h1, w1.w, a1.w);
            a2.x = fmaf(h2, w2.x, a2.x); a2.y = fmaf(h2, w2.y, a2.y);
            a2.z = fmaf(h2, w2.z, a2.z); a2.w = fmaf(h2, w2.w, a2.w);
            a3.x = fmaf(h3, w3.x, a3.x); a3.y = fmaf(h3, w3.y, a3.y);
            a3.z = fmaf(h3, w3.z, a3.z); a3.w = fmaf(h3, w3.w, a3.w);
        }
        red[t] = f4add(f4add(a0, a1), f4add(a2, a3));

        // gate on M (g_wfsum ready)
        if (t == 0) {
            while (atomicAdd(&g_c3, 0) < 16) __nanosleep(32);
            __threadfence();
        }
        __syncthreads();

        // load Wfsum (16KB) into padded smem: 4 independent float4 loads/thread
        const float4* ws4 = reinterpret_cast<const float4*>(g_wfsum);
#pragma unroll
        for (int p = 0; p < 4; ++p) {
            const int idx = p * 256 + t;         // float4 idx in [0,1024)
            const int cp  = idx >> 4;
            const int cc4 = idx & 15;
            const float4 v = __ldg(ws4 + idx);
            float* w = wfs + cp * 65 + 4 * cc4;
            w[0] = v.x; w[1] = v.y; w[2] = v.z; w[3] = v.w;
        }
        __syncthreads();

        // reduce who partials
        if (t < 128) red[t] = f4add(red[t], red[t + 128]);
        __syncthreads();
        if (t < 64)  red[t] = f4add(red[t], red[t + 64]);
        __syncthreads();
        if (t < 32)  red[t] = f4add(red[t], red[t + 32]);
        __syncthreads();
        if (t < 16) {
            const float4 s = f4add(red[t], red[t + 16]);
            who_s[4 * t + 0] = s.x;
            who_s[4 * t + 1] = s.y;
            who_s[4 * t + 2] = s.z;
            who_s[4 * t + 3] = s.w;
        }
        __syncthreads();

        // final GEMV: t = part*64 + cp (padded wfs rows -> conflict-free)
        const int cp   = t & 63;
        const int part = t >> 6;
        float a = 0.f;
#pragma unroll
        for (int j = 0; j < 16; ++j) {
            const int c = part * 16 + j;
            a = fmaf(who_s[c], wfs[cp * 65 + c], a);
        }
        red2[t] = a;
        __syncthreads();

        if (t < 64) {
            out[b * 64 + t] = red2[t] + red2[64 + t] + red2[128 + t] + red2[192 + t]
                            + __ldg(bf + t);
        }
        __syncthreads();

        // last consumer resets counters for the next graph replay
        if (t == 0) {
            const int d = atomicAdd(&g_done, 1);
            if (d == 31) {
                atomicExch(&g_c1, 0);
                atomicExch(&g_c2, 0);
                atomicExch(&g_c3, 0);
                atomicExch(&g_done, 0);
            }
        }
    }
}

// ---------------------------------------------------------------------------
extern "C" void kernel_launch(void* const* d_in, const int* in_sizes, int n_in,
                              void* d_out, int out_size)
{
    // metadata order: x, W_heads, a1_heads, a2_heads, W_out, a1_out, a2_out, Wf, bf
    const float* x      = (const float*)d_in[0];
    const float* Wheads = (const float*)d_in[1];
    const float* Wout   = (const float*)d_in[4];
    const float* Wf     = (const float*)d_in[7];
    const float* bf     = (const float*)d_in[8];
    float* out = (float*)d_out;

    k_fused<<<816, 256>>>(x, Wheads, Wout, Wf, bf, out);
}